// round 13
// baseline (speedup 1.0000x reference)
#include <cuda_runtime.h>
#include <cstdint>

#define N_NODES 50000
#define E_EDGES 600000
#define FDIM 128
#define OUTD 12

// ---------------- scratch (device globals; no runtime allocation) ------------
__device__ float g_deg[N_NODES];
__device__ float g_dinv[N_NODES];
__device__ float g_agg[(size_t)N_NODES * FDIM];          // A_norm @ x
__device__ float g_Wcomb[3][256 * FDIM];                 // [Mg ; Lg_bot] per gate
__device__ float g_c[3][FDIM];                           // folded biases

// ---------------- weight folding: Mg = Wg @ Lg_top ----------------------------
__global__ void __launch_bounds__(256)
k_prep_m(const float* __restrict__ Wz, const float* __restrict__ Wr,
         const float* __restrict__ Wh, const float* __restrict__ Lz,
         const float* __restrict__ Lr, const float* __restrict__ Lh) {
    int gate = blockIdx.y;
    const float* W = (gate == 0) ? Wz : (gate == 1) ? Wr : Wh;
    const float* L = (gate == 0) ? Lz : (gate == 1) ? Lr : Lh;
    float* C = g_Wcomb[gate];

    __shared__ float As[64][16];
    __shared__ float Ls[16][128];
    int tid = threadIdx.x, tx = tid & 31, ty = tid >> 5;
    int row0 = blockIdx.x * 64;
    float acc[8][4] = {};

    for (int kk = 0; kk < 128; kk += 16) {
        {
            int r = tid >> 2, c4 = tid & 3;
            *(float4*)&As[r][c4 * 4] =
                *(const float4*)(W + (size_t)(row0 + r) * FDIM + kk + c4 * 4);
        }
        #pragma unroll
        for (int t = 0; t < 2; t++) {
            int idx = tid + t * 256;
            int r = idx >> 5, c = (idx & 31) * 4;
            *(float4*)&Ls[r][c] = *(const float4*)(L + (size_t)(kk + r) * FDIM + c);
        }
        __syncthreads();
        #pragma unroll
        for (int k = 0; k < 16; k++) {
            float4 wv = *(float4*)&Ls[k][tx * 4];
            #pragma unroll
            for (int i = 0; i < 8; i++) {
                float a = As[ty * 8 + i][k];
                acc[i][0] += a * wv.x; acc[i][1] += a * wv.y;
                acc[i][2] += a * wv.z; acc[i][3] += a * wv.w;
            }
        }
        __syncthreads();
    }
    #pragma unroll
    for (int i = 0; i < 8; i++) {
        int row = row0 + ty * 8 + i;
        *(float4*)(C + (size_t)row * FDIM + tx * 4) =
            make_float4(acc[i][0], acc[i][1], acc[i][2], acc[i][3]);
    }
}

__global__ void __launch_bounds__(256)
k_prep_rest(const float* __restrict__ Lz, const float* __restrict__ Lr,
            const float* __restrict__ Lh,
            const float* __restrict__ bz, const float* __restrict__ br,
            const float* __restrict__ bh,
            const float* __restrict__ lbz, const float* __restrict__ lbr,
            const float* __restrict__ lbh) {
    int g = blockIdx.x;
    const float* L  = (g == 0) ? Lz : (g == 1) ? Lr : Lh;
    const float* b  = (g == 0) ? bz : (g == 1) ? br : bh;
    const float* lb = (g == 0) ? lbz : (g == 1) ? lbr : lbh;
    float* C = g_Wcomb[g];
    int tid = threadIdx.x;
    for (int i = tid; i < 128 * FDIM / 4; i += 256)
        ((float4*)(C + 128 * FDIM))[i] = ((const float4*)(L + 128 * FDIM))[i];
    if (tid < FDIM) {
        float a = lb[tid];
        #pragma unroll 8
        for (int k = 0; k < 128; k++) a += b[k] * L[(size_t)k * FDIM + tid];
        g_c[g][tid] = a;
    }
}

// ---------------- degree / norm / aggregation ---------------------------------
__global__ void k_init_deg() {
    int i = blockIdx.x * blockDim.x + threadIdx.x;
    if (i < N_NODES) g_deg[i] = 1.0f;
}

__global__ void k_deg_acc(const int* __restrict__ ei,
                          const float* __restrict__ ew) {
    for (int e = blockIdx.x * blockDim.x + threadIdx.x; e < E_EDGES;
         e += gridDim.x * blockDim.x) {
        int d = ei[E_EDGES + e];
        atomicAdd(&g_deg[d], ew[e]);
    }
}

__global__ void k_dinv_self(const float* __restrict__ x) {
    int warp = (blockIdx.x * blockDim.x + threadIdx.x) >> 5;
    int lane = threadIdx.x & 31;
    if (warp >= N_NODES) return;
    float s;
    if (lane == 0) {
        float dg = g_deg[warp];
        s = (dg > 0.0f) ? rsqrtf(dg) : 0.0f;
        g_dinv[warp] = s;
    }
    s = __shfl_sync(0xffffffffu, s, 0);
    float s2 = s * s;
    size_t off = (size_t)warp * FDIM + lane * 4;
    float4 v = *(const float4*)(x + off);
    v.x *= s2; v.y *= s2; v.z *= s2; v.w *= s2;
    *(float4*)(g_agg + off) = v;
}

__global__ void k_edge_agg(const int* __restrict__ ei,
                           const float* __restrict__ ew,
                           const float* __restrict__ x) {
    int warp = (blockIdx.x * blockDim.x + threadIdx.x) >> 5;
    int lane = threadIdx.x & 31;
    if (warp >= E_EDGES) return;
    int s = 0, d = 0;
    float norm = 0.0f;
    if (lane == 0) {
        s = ei[warp];
        d = ei[E_EDGES + warp];
        norm = g_dinv[s] * ew[warp] * g_dinv[d];
    }
    s = __shfl_sync(0xffffffffu, s, 0);
    d = __shfl_sync(0xffffffffu, d, 0);
    norm = __shfl_sync(0xffffffffu, norm, 0);
    float4 v = *(const float4*)(x + (size_t)s * FDIM + lane * 4);
    float* p = g_agg + (size_t)d * FDIM + lane * 4;
    asm volatile("red.global.add.v4.f32 [%0], {%1,%2,%3,%4};"
                 :: "l"(p), "f"(v.x * norm), "f"(v.y * norm),
                    "f"(v.z * norm), "f"(v.w * norm)
                 : "memory");
}

// ===================== fused cell kernel (tf32 TC) ============================
__device__ __forceinline__ void cp16(void* s, const void* g, bool pred) {
    unsigned sa = (unsigned)__cvta_generic_to_shared(s);
    int sz = pred ? 16 : 0;
    asm volatile("cp.async.cg.shared.global [%0], [%1], 16, %2;\n"
                 :: "r"(sa), "l"(g), "r"(sz));
}
#define CP_COMMIT asm volatile("cp.async.commit_group;\n" ::: "memory")
#define CP_WAIT1  asm volatile("cp.async.wait_group 1;\n" ::: "memory")
#define CP_WAIT0  asm volatile("cp.async.wait_group 0;\n" ::: "memory")

__device__ __forceinline__ void mma8(float* c, unsigned a0, unsigned a1,
                                     unsigned a2, unsigned a3,
                                     unsigned b0, unsigned b1) {
    asm volatile("mma.sync.aligned.m16n8k8.row.col.f32.tf32.tf32.f32 "
        "{%0,%1,%2,%3},{%4,%5,%6,%7},{%8,%9},{%0,%1,%2,%3};"
        : "+f"(c[0]), "+f"(c[1]), "+f"(c[2]), "+f"(c[3])
        : "r"(a0), "r"(a1), "r"(a2), "r"(a3), "r"(b0), "r"(b1));
}

// smem layout (floats): As[2][128][20]=5120 | Ws[2][16][264]=8448 |
//                       HRs[128][132]=16896 | Zs[128][132]=16896 | Wos 1548
#define SM_AS   0
#define SM_WS   5120
#define SM_HRS  13568
#define SM_ZS   30464
#define SM_WOS  47360
#define SM_FLOATS 48908
#define SM_BYTES (SM_FLOATS * 4)

#define LOAD_A(buf, Asrc, colbase)                                         \
    _Pragma("unroll")                                                      \
    for (int t = 0; t < 2; t++) {                                          \
        int idx = tid + t * 256;                                           \
        int r = idx >> 2, c = (idx & 3) * 4;                               \
        cp16(&As[(buf) * 2560 + r * 20 + c],                               \
             (Asrc) + (size_t)(row0 + r) * FDIM + (colbase) + c,           \
             (row0 + r) < N_NODES);                                        \
    }

// phase-1 W: 16 x 256 (z cols 0..127, r cols 128..255)
#define LOAD_W1(buf, kb)                                                   \
    _Pragma("unroll")                                                      \
    for (int t = 0; t < 4; t++) {                                          \
        int idx = tid + t * 256;                                           \
        int r = idx >> 6, c = (idx & 63) * 4;                              \
        const float* src = (c < 128)                                       \
            ? g_Wcomb[0] + (size_t)((kb) + r) * FDIM + c                   \
            : g_Wcomb[1] + (size_t)((kb) + r) * FDIM + (c - 128);          \
        cp16(&Ws[(buf) * 4224 + r * 264 + c], src, true);                  \
    }

// phase-2 W: 16 x 128
#define LOAD_W2(buf, kb)                                                   \
    _Pragma("unroll")                                                      \
    for (int t = 0; t < 2; t++) {                                          \
        int idx = tid + t * 256;                                           \
        int r = idx >> 5, c = (idx & 31) * 4;                              \
        cp16(&Ws[(buf) * 4224 + r * 264 + c],                              \
             g_Wcomb[2] + (size_t)((kb) + r) * FDIM + c, true);            \
    }

#define P1_COMPUTE(buf)                                                    \
    _Pragma("unroll")                                                      \
    for (int ks = 0; ks < 16; ks += 8) {                                   \
        unsigned af[4][4], bf[8][2];                                       \
        _Pragma("unroll")                                                  \
        for (int m = 0; m < 4; m++) {                                      \
            int r = wr1 + 16 * m + qid;                                    \
            const float* ap = As + (buf) * 2560;                           \
            af[m][0] = __float_as_uint(ap[r * 20 + ks + qtid]);            \
            af[m][1] = __float_as_uint(ap[(r + 8) * 20 + ks + qtid]);      \
            af[m][2] = __float_as_uint(ap[r * 20 + ks + qtid + 4]);        \
            af[m][3] = __float_as_uint(ap[(r + 8) * 20 + ks + qtid + 4]);  \
        }                                                                  \
        _Pragma("unroll")                                                  \
        for (int n = 0; n < 8; n++) {                                      \
            int cc = wc1 + 8 * n + qid;                                    \
            const float* wp = Ws + (buf) * 4224;                           \
            bf[n][0] = __float_as_uint(wp[(ks + qtid) * 264 + cc]);        \
            bf[n][1] = __float_as_uint(wp[(ks + qtid + 4) * 264 + cc]);    \
        }                                                                  \
        _Pragma("unroll")                                                  \
        for (int m = 0; m < 4; m++)                                        \
            _Pragma("unroll")                                              \
            for (int n = 0; n < 8; n++)                                    \
                mma8(acc1[m][n], af[m][0], af[m][1], af[m][2], af[m][3],   \
                     bf[n][0], bf[n][1]);                                  \
    }

#define P2_FRAG_B(buf)                                                     \
        unsigned bf[4][2];                                                 \
        _Pragma("unroll")                                                  \
        for (int n = 0; n < 4; n++) {                                      \
            int cc = wc2 + 8 * n + qid;                                    \
            const float* wp = Ws + (buf) * 4224;                           \
            bf[n][0] = __float_as_uint(wp[(ks + qtid) * 264 + cc]);        \
            bf[n][1] = __float_as_uint(wp[(ks + qtid + 4) * 264 + cc]);    \
        }

#define P2_MMA                                                             \
        _Pragma("unroll")                                                  \
        for (int m = 0; m < 4; m++)                                        \
            _Pragma("unroll")                                              \
            for (int n = 0; n < 4; n++)                                    \
                mma8(acc2[m][n], af[m][0], af[m][1], af[m][2], af[m][3],   \
                     bf[n][0], bf[n][1]);

__global__ void __launch_bounds__(256, 1)
k_cell(const float* __restrict__ H, const float* __restrict__ Wo,
       const float* __restrict__ bo,
       float* __restrict__ y_out, float* __restrict__ h_out) {
    extern __shared__ float sm_[];
    float* As  = sm_ + SM_AS;
    float* Ws  = sm_ + SM_WS;
    float* HRs = sm_ + SM_HRS;
    float* Zs  = sm_ + SM_ZS;
    float* Wos = sm_ + SM_WOS;

    int tid = threadIdx.x;
    int lane = tid & 31, wid = tid >> 5;
    int qid = lane >> 2, qtid = lane & 3;
    int row0 = blockIdx.x * 128;

    // ---------------- phase 1: [agg|H] @ [Wc_z ‖ Wc_r] -> Z, H*R -------------
    {
        int wr1 = (wid >> 2) * 64, wc1 = (wid & 3) * 64;
        float acc1[4][8][4] = {};

        LOAD_A(0, g_agg, 0)
        LOAD_W1(0, 0)
        CP_COMMIT;
        for (int kk = 0; kk < 16; kk++) {
            if (kk < 15) {
                int nk = kk + 1;
                const float* Asrc = (nk < 8) ? g_agg : H;
                LOAD_A(nk & 1, Asrc, (nk & 7) * 16)
                LOAD_W1(nk & 1, nk * 16)
                CP_COMMIT; CP_WAIT1;
            } else { CP_WAIT0; }
            __syncthreads();
            P1_COMPUTE(kk & 1)
            __syncthreads();
        }

        const float* cz = g_c[0];
        const float* cr = g_c[1];
        #pragma unroll
        for (int m = 0; m < 4; m++) {
            #pragma unroll
            for (int n = 0; n < 8; n++) {
                int col = wc1 + 8 * n + 2 * qtid;
                #pragma unroll
                for (int h = 0; h < 2; h++) {
                    int rl = wr1 + 16 * m + qid + 8 * h;
                    int grow = row0 + rl;
                    float v0 = acc1[m][n][2 * h], v1 = acc1[m][n][2 * h + 1];
                    if (col < 128) {
                        Zs[rl * 132 + col]     = 1.0f / (1.0f + __expf(-(v0 + cz[col])));
                        Zs[rl * 132 + col + 1] = 1.0f / (1.0f + __expf(-(v1 + cz[col + 1])));
                    } else {
                        int c2 = col - 128;
                        float r0 = 1.0f / (1.0f + __expf(-(v0 + cr[c2])));
                        float r1 = 1.0f / (1.0f + __expf(-(v1 + cr[c2 + 1])));
                        float2 hv = make_float2(0.f, 0.f);
                        if (grow < N_NODES)
                            hv = *(const float2*)(H + (size_t)grow * FDIM + c2);
                        HRs[rl * 132 + c2]     = hv.x * r0;
                        HRs[rl * 132 + c2 + 1] = hv.y * r1;
                    }
                }
            }
        }
    }
    __syncthreads();

    // ---------------- phase 2: [agg|HR] @ Wc_h -> Ht, h, relu(h) -------------
    {
        int wr2 = (wid >> 2) * 64, wc2 = (wid & 3) * 32;
        float acc2[4][4][4] = {};

        LOAD_A(0, g_agg, 0)
        LOAD_W2(0, 0)
        CP_COMMIT;
        for (int kk = 0; kk < 16; kk++) {
            if (kk < 15) {
                int nk = kk + 1;
                if (nk < 8) { LOAD_A(nk & 1, g_agg, nk * 16) }
                LOAD_W2(nk & 1, nk * 16)
                CP_COMMIT; CP_WAIT1;
            } else { CP_WAIT0; }
            __syncthreads();
            if (kk < 8) {
                int buf = kk & 1;
                #pragma unroll
                for (int ks = 0; ks < 16; ks += 8) {
                    unsigned af[4][4];
                    #pragma unroll
                    for (int m = 0; m < 4; m++) {
                        int r = wr2 + 16 * m + qid;
                        const float* ap = As + buf * 2560;
                        af[m][0] = __float_as_uint(ap[r * 20 + ks + qtid]);
                        af[m][1] = __float_as_uint(ap[(r + 8) * 20 + ks + qtid]);
                        af[m][2] = __float_as_uint(ap[r * 20 + ks + qtid + 4]);
                        af[m][3] = __float_as_uint(ap[(r + 8) * 20 + ks + qtid + 4]);
                    }
                    P2_FRAG_B(buf)
                    P2_MMA
                }
            } else {
                int buf = kk & 1;
                int colbase = (kk - 8) * 16;
                #pragma unroll
                for (int ks = 0; ks < 16; ks += 8) {
                    unsigned af[4][4];
                    #pragma unroll
                    for (int m = 0; m < 4; m++) {
                        int r = wr2 + 16 * m + qid;
                        af[m][0] = __float_as_uint(HRs[r * 132 + colbase + ks + qtid]);
                        af[m][1] = __float_as_uint(HRs[(r + 8) * 132 + colbase + ks + qtid]);
                        af[m][2] = __float_as_uint(HRs[r * 132 + colbase + ks + qtid + 4]);
                        af[m][3] = __float_as_uint(HRs[(r + 8) * 132 + colbase + ks + qtid + 4]);
                    }
                    P2_FRAG_B(buf)
                    P2_MMA
                }
            }
            __syncthreads();
        }

        const float* ch = g_c[2];
        #pragma unroll
        for (int m = 0; m < 4; m++) {
            #pragma unroll
            for (int n = 0; n < 4; n++) {
                int col = wc2 + 8 * n + 2 * qtid;
                float b0 = ch[col], b1 = ch[col + 1];
                #pragma unroll
                for (int h = 0; h < 2; h++) {
                    int rl = wr2 + 16 * m + qid + 8 * h;
                    int grow = row0 + rl;
                    float x0 = acc2[m][n][2 * h] + b0;
                    float x1 = acc2[m][n][2 * h + 1] + b1;
                    float t0 = 1.0f - 2.0f / (__expf(2.0f * x0) + 1.0f);
                    float t1 = 1.0f - 2.0f / (__expf(2.0f * x1) + 1.0f);
                    float z0 = Zs[rl * 132 + col], z1 = Zs[rl * 132 + col + 1];
                    float2 hv = make_float2(0.f, 0.f);
                    if (grow < N_NODES)
                        hv = *(const float2*)(H + (size_t)grow * FDIM + col);
                    float h0 = z0 * hv.x + (1.0f - z0) * t0;
                    float h1 = z1 * hv.y + (1.0f - z1) * t1;
                    if (grow < N_NODES)
                        *(float2*)(h_out + (size_t)grow * FDIM + col) = make_float2(h0, h1);
                    HRs[rl * 132 + col]     = fmaxf(h0, 0.0f);
                    HRs[rl * 132 + col + 1] = fmaxf(h1, 0.0f);
                }
            }
        }
    }
    __syncthreads();

    // ---------------- phase 3: y = relu(h) @ Wo + bo --------------------------
    for (int t = tid; t < FDIM * OUTD; t += 256) Wos[t] = Wo[t];
    if (tid < OUTD) Wos[FDIM * OUTD + tid] = bo[tid];
    __syncthreads();
    {
        int rl = tid >> 1;
        int og = (tid & 1) * 6;
        int grow = row0 + rl;
        if (grow < N_NODES) {
            float a[6] = {};
            #pragma unroll 8
            for (int k = 0; k < FDIM; k++) {
                float hv = HRs[rl * 132 + k];
                #pragma unroll
                for (int o = 0; o < 6; o++)
                    a[o] += hv * Wos[k * OUTD + og + o];
            }
            #pragma unroll
            for (int o = 0; o < 6; o++)
                y_out[(size_t)grow * OUTD + og + o] = a[o] + Wos[FDIM * OUTD + og + o];
        }
    }
}

// ---------------- launch ------------------------------------------------------
extern "C" void kernel_launch(void* const* d_in, const int* in_sizes, int n_in,
                              void* d_out, int out_size) {
    const float* x  = (const float*)d_in[0];
    const int*   ei = (const int*)d_in[1];
    const float* ew = (const float*)d_in[2];
    const float* H  = (const float*)d_in[3];
    const float* Wz = (const float*)d_in[4];
    const float* bz = (const float*)d_in[5];
    const float* Wr = (const float*)d_in[6];
    const float* br = (const float*)d_in[7];
    const float* Wh = (const float*)d_in[8];
    const float* bh = (const float*)d_in[9];
    const float* Lz = (const float*)d_in[10];
    const float* lbz = (const float*)d_in[11];
    const float* Lr = (const float*)d_in[12];
    const float* lbr = (const float*)d_in[13];
    const float* Lh = (const float*)d_in[14];
    const float* lbh = (const float*)d_in[15];
    const float* Wo = (const float*)d_in[16];
    const float* bo = (const float*)d_in[17];

    float* y_out = (float*)d_out;                           // (N, 12)
    float* h_out = (float*)d_out + (size_t)N_NODES * OUTD;  // (N, 128)

    cudaFuncSetAttribute(k_cell, cudaFuncAttributeMaxDynamicSharedMemorySize,
                         SM_BYTES);

    int nblk = (N_NODES + 127) / 128;   // 391

    k_prep_m<<<dim3(2, 3), 256>>>(Wz, Wr, Wh, Lz, Lr, Lh);
    k_prep_rest<<<3, 256>>>(Lz, Lr, Lh, bz, br, bh, lbz, lbr, lbh);
    k_init_deg<<<(N_NODES + 255) / 256, 256>>>();
    k_deg_acc<<<592, 256>>>(ei, ew);
    k_dinv_self<<<(N_NODES * 32 + 255) / 256, 256>>>(x);
    k_edge_agg<<<(E_EDGES * 32 + 255) / 256, 256>>>(ei, ew, x);
    k_cell<<<nblk, 256, SM_BYTES>>>(H, Wo, bo, y_out, h_out);
}

// round 14
// speedup vs baseline: 1.0548x; 1.0548x over previous
#include <cuda_runtime.h>
#include <cstdint>

#define N_NODES 50000
#define E_EDGES 600000
#define FDIM 128
#define OUTD 12

// ---------------- scratch (device globals; no runtime allocation) ------------
__device__ float g_deg[N_NODES];
__device__ float g_dinv[N_NODES];
__device__ float g_agg[(size_t)N_NODES * FDIM];          // A_norm @ x
__device__ float g_Z[(size_t)N_NODES * FDIM];
__device__ float g_R[(size_t)N_NODES * FDIM];            // stores H*R (fused)
__device__ float g_relu[(size_t)N_NODES * FDIM];         // relu(h)
__device__ float g_Wcomb[3][256 * FDIM];                 // [Mg ; Lg_bot] per gate
__device__ float g_Wzr[256 * 256];                       // packed [Wc_z ‖ Wc_r]
__device__ float g_c[3][FDIM];                           // folded biases

// ---------------- weight folding: Mg = Wg @ Lg_top ----------------------------
__global__ void __launch_bounds__(256)
k_prep_m(const float* __restrict__ Wz, const float* __restrict__ Wr,
         const float* __restrict__ Wh, const float* __restrict__ Lz,
         const float* __restrict__ Lr, const float* __restrict__ Lh) {
    int gate = blockIdx.y;
    const float* W = (gate == 0) ? Wz : (gate == 1) ? Wr : Wh;
    const float* L = (gate == 0) ? Lz : (gate == 1) ? Lr : Lh;
    float* C = g_Wcomb[gate];

    __shared__ float As[64][16];
    __shared__ float Ls[16][128];
    int tid = threadIdx.x, tx = tid & 31, ty = tid >> 5;
    int row0 = blockIdx.x * 64;
    float acc[8][4] = {};

    for (int kk = 0; kk < 128; kk += 16) {
        {
            int r = tid >> 2, c4 = tid & 3;
            *(float4*)&As[r][c4 * 4] =
                *(const float4*)(W + (size_t)(row0 + r) * FDIM + kk + c4 * 4);
        }
        #pragma unroll
        for (int t = 0; t < 2; t++) {
            int idx = tid + t * 256;
            int r = idx >> 5, c = (idx & 31) * 4;
            *(float4*)&Ls[r][c] = *(const float4*)(L + (size_t)(kk + r) * FDIM + c);
        }
        __syncthreads();
        #pragma unroll
        for (int k = 0; k < 16; k++) {
            float4 wv = *(float4*)&Ls[k][tx * 4];
            #pragma unroll
            for (int i = 0; i < 8; i++) {
                float a = As[ty * 8 + i][k];
                acc[i][0] += a * wv.x; acc[i][1] += a * wv.y;
                acc[i][2] += a * wv.z; acc[i][3] += a * wv.w;
            }
        }
        __syncthreads();
    }
    #pragma unroll
    for (int i = 0; i < 8; i++) {
        int row = row0 + ty * 8 + i;
        *(float4*)(C + (size_t)row * FDIM + tx * 4) =
            make_float4(acc[i][0], acc[i][1], acc[i][2], acc[i][3]);
    }
}

__global__ void __launch_bounds__(256)
k_prep_rest(const float* __restrict__ Lz, const float* __restrict__ Lr,
            const float* __restrict__ Lh,
            const float* __restrict__ bz, const float* __restrict__ br,
            const float* __restrict__ bh,
            const float* __restrict__ lbz, const float* __restrict__ lbr,
            const float* __restrict__ lbh) {
    int g = blockIdx.x;
    const float* L  = (g == 0) ? Lz : (g == 1) ? Lr : Lh;
    const float* b  = (g == 0) ? bz : (g == 1) ? br : bh;
    const float* lb = (g == 0) ? lbz : (g == 1) ? lbr : lbh;
    float* C = g_Wcomb[g];
    int tid = threadIdx.x;
    for (int i = tid; i < 128 * FDIM / 4; i += 256)
        ((float4*)(C + 128 * FDIM))[i] = ((const float4*)(L + 128 * FDIM))[i];
    if (tid < FDIM) {
        float a = lb[tid];
        #pragma unroll 8
        for (int k = 0; k < 128; k++) a += b[k] * L[(size_t)k * FDIM + tid];
        g_c[g][tid] = a;
    }
}

// pack g_Wzr[r][c] = (c<128) ? Wcomb0[r][c] : Wcomb1[r][c-128]
__global__ void __launch_bounds__(256)
k_prep_zr() {
    int i = blockIdx.x * blockDim.x + threadIdx.x;   // float4 index
    if (i >= 256 * 64) return;
    int r = i >> 6, c4 = (i & 63) * 4;
    float4 v = (c4 < 128)
        ? *(const float4*)(g_Wcomb[0] + (size_t)r * FDIM + c4)
        : *(const float4*)(g_Wcomb[1] + (size_t)r * FDIM + (c4 - 128));
    *(float4*)(g_Wzr + (size_t)r * 256 + c4) = v;
}

// ---------------- degree / norm / aggregation ---------------------------------
__global__ void k_init_deg() {
    int i = blockIdx.x * blockDim.x + threadIdx.x;
    if (i < N_NODES) g_deg[i] = 1.0f;
}

__global__ void k_deg_acc(const int* __restrict__ ei,
                          const float* __restrict__ ew) {
    for (int e = blockIdx.x * blockDim.x + threadIdx.x; e < E_EDGES;
         e += gridDim.x * blockDim.x) {
        int d = ei[E_EDGES + e];
        atomicAdd(&g_deg[d], ew[e]);
    }
}

__global__ void k_dinv_self(const float* __restrict__ x) {
    int warp = (blockIdx.x * blockDim.x + threadIdx.x) >> 5;
    int lane = threadIdx.x & 31;
    if (warp >= N_NODES) return;
    float s;
    if (lane == 0) {
        float dg = g_deg[warp];
        s = (dg > 0.0f) ? rsqrtf(dg) : 0.0f;
        g_dinv[warp] = s;
    }
    s = __shfl_sync(0xffffffffu, s, 0);
    float s2 = s * s;
    size_t off = (size_t)warp * FDIM + lane * 4;
    float4 v = *(const float4*)(x + off);
    v.x *= s2; v.y *= s2; v.z *= s2; v.w *= s2;
    *(float4*)(g_agg + off) = v;
}

__global__ void k_edge_agg(const int* __restrict__ ei,
                           const float* __restrict__ ew,
                           const float* __restrict__ x) {
    int warp = (blockIdx.x * blockDim.x + threadIdx.x) >> 5;
    int lane = threadIdx.x & 31;
    if (warp >= E_EDGES) return;
    int s = 0, d = 0;
    float norm = 0.0f;
    if (lane == 0) {
        s = ei[warp];
        d = ei[E_EDGES + warp];
        norm = g_dinv[s] * ew[warp] * g_dinv[d];
    }
    s = __shfl_sync(0xffffffffu, s, 0);
    d = __shfl_sync(0xffffffffu, d, 0);
    norm = __shfl_sync(0xffffffffu, norm, 0);
    float4 v = *(const float4*)(x + (size_t)s * FDIM + lane * 4);
    float* p = g_agg + (size_t)d * FDIM + lane * 4;
    asm volatile("red.global.add.v4.f32 [%0], {%1,%2,%3,%4};"
                 :: "l"(p), "f"(v.x * norm), "f"(v.y * norm),
                    "f"(v.z * norm), "f"(v.w * norm)
                 : "memory");
}

// ============= tf32 tensor-core GEMM, cp.async double-buffered ================
__device__ __forceinline__ void cp16(void* s, const void* g, bool pred) {
    unsigned sa = (unsigned)__cvta_generic_to_shared(s);
    int sz = pred ? 16 : 0;
    asm volatile("cp.async.cg.shared.global [%0], [%1], 16, %2;\n"
                 :: "r"(sa), "l"(g), "r"(sz));
}
#define CP_COMMIT asm volatile("cp.async.commit_group;\n" ::: "memory")
#define CP_WAIT1  asm volatile("cp.async.wait_group 1;\n" ::: "memory")
#define CP_WAIT0  asm volatile("cp.async.wait_group 0;\n" ::: "memory")

__device__ __forceinline__ void mma8(float* c, unsigned a0, unsigned a1,
                                     unsigned a2, unsigned a3,
                                     unsigned b0, unsigned b1) {
    asm volatile("mma.sync.aligned.m16n8k8.row.col.f32.tf32.tf32.f32 "
        "{%0,%1,%2,%3},{%4,%5,%6,%7},{%8,%9},{%0,%1,%2,%3};"
        : "+f"(c[0]), "+f"(c[1]), "+f"(c[2]), "+f"(c[3])
        : "r"(a0), "r"(a1), "r"(a2), "r"(a3), "r"(b0), "r"(b1));
}

// ------- merged Z+R GEMM: [agg|H] @ [Wc_z‖Wc_r]; 512 thr, warp tile 32x64 ----
// smem: As[2][128][20]=5120 fl | Ws[2][16][264]=8448 fl  -> 54.3KB dynamic
#define ZR_SM_FLOATS (5120 + 8448)

__global__ void __launch_bounds__(512, 1)
k_zr(const float* __restrict__ H) {
    extern __shared__ float sm_[];
    float* As = sm_;
    float* Ws = sm_ + 5120;

    int tid = threadIdx.x;
    int lane = tid & 31, wid = tid >> 5;         // 16 warps: 4 row x 4 col
    int qid = lane >> 2, qtid = lane & 3;
    int wr = (wid >> 2) * 32, wc = (wid & 3) * 64;
    int row0 = blockIdx.x * 128;
    float acc[2][8][4] = {};

#define ZR_LOAD_A(buf, Asrc, colbase)                                      \
    {                                                                      \
        int r = tid >> 2, c = (tid & 3) * 4;                               \
        cp16(&As[(buf) * 2560 + r * 20 + c],                               \
             (Asrc) + (size_t)(row0 + r) * FDIM + (colbase) + c,           \
             (row0 + r) < N_NODES);                                        \
    }
#define ZR_LOAD_W(buf, kb)                                                 \
    _Pragma("unroll")                                                      \
    for (int t = 0; t < 2; t++) {                                          \
        int idx = tid + t * 512;                                           \
        int r = idx >> 6, c = (idx & 63) * 4;                              \
        cp16(&Ws[(buf) * 4224 + r * 264 + c],                              \
             g_Wzr + (size_t)((kb) + r) * 256 + c, true);                  \
    }

    ZR_LOAD_A(0, g_agg, 0)
    ZR_LOAD_W(0, 0)
    CP_COMMIT;
    for (int kk = 0; kk < 16; kk++) {
        if (kk < 15) {
            int nk = kk + 1;
            const float* Asrc = (nk < 8) ? g_agg : H;
            ZR_LOAD_A(nk & 1, Asrc, (nk & 7) * 16)
            ZR_LOAD_W(nk & 1, nk * 16)
            CP_COMMIT; CP_WAIT1;
        } else { CP_WAIT0; }
        __syncthreads();
        {
            int buf = kk & 1;
            #pragma unroll
            for (int ks = 0; ks < 16; ks += 8) {
                unsigned af[2][4], bf[8][2];
                #pragma unroll
                for (int m = 0; m < 2; m++) {
                    int r = wr + 16 * m + qid;
                    const float* ap = As + buf * 2560;
                    af[m][0] = __float_as_uint(ap[r * 20 + ks + qtid]);
                    af[m][1] = __float_as_uint(ap[(r + 8) * 20 + ks + qtid]);
                    af[m][2] = __float_as_uint(ap[r * 20 + ks + qtid + 4]);
                    af[m][3] = __float_as_uint(ap[(r + 8) * 20 + ks + qtid + 4]);
                }
                #pragma unroll
                for (int n = 0; n < 8; n++) {
                    int cc = wc + 8 * n + qid;
                    const float* wp = Ws + buf * 4224;
                    bf[n][0] = __float_as_uint(wp[(ks + qtid) * 264 + cc]);
                    bf[n][1] = __float_as_uint(wp[(ks + qtid + 4) * 264 + cc]);
                }
                #pragma unroll
                for (int m = 0; m < 2; m++)
                    #pragma unroll
                    for (int n = 0; n < 8; n++)
                        mma8(acc[m][n], af[m][0], af[m][1], af[m][2], af[m][3],
                             bf[n][0], bf[n][1]);
            }
        }
        __syncthreads();
    }

    const float* cz = g_c[0];
    const float* cr = g_c[1];
    #pragma unroll
    for (int m = 0; m < 2; m++) {
        #pragma unroll
        for (int n = 0; n < 8; n++) {
            int col = wc + 8 * n + 2 * qtid;
            #pragma unroll
            for (int h = 0; h < 2; h++) {
                int grow = row0 + wr + 16 * m + qid + 8 * h;
                if (grow < N_NODES) {
                    float v0 = acc[m][n][2 * h], v1 = acc[m][n][2 * h + 1];
                    if (col < 128) {
                        float2 o;
                        o.x = 1.0f / (1.0f + __expf(-(v0 + cz[col])));
                        o.y = 1.0f / (1.0f + __expf(-(v1 + cz[col + 1])));
                        *(float2*)(g_Z + (size_t)grow * FDIM + col) = o;
                    } else {
                        int c2 = col - 128;
                        float r0 = 1.0f / (1.0f + __expf(-(v0 + cr[c2])));
                        float r1 = 1.0f / (1.0f + __expf(-(v1 + cr[c2 + 1])));
                        float2 hv = *(const float2*)(H + (size_t)grow * FDIM + c2);
                        *(float2*)(g_R + (size_t)grow * FDIM + c2) =
                            make_float2(hv.x * r0, hv.y * r1);
                    }
                }
            }
        }
    }
}

// ---- final GEMM (unchanged R12): 256 thr, 2 CTA/SM, warp tile 64x32 ----------
#define TC_DECL                                                            \
    __shared__ float As[2][128][20];                                       \
    __shared__ float Ws[2][16][136];                                       \
    int tid = threadIdx.x;                                                 \
    int lane = tid & 31, wid = tid >> 5;                                   \
    int qid = lane >> 2, qtid = lane & 3;                                  \
    int wr = (wid >> 2) * 64, wc = (wid & 3) * 32;                         \
    int row0 = blockIdx.x * 128;                                           \
    float acc[4][4][4] = {};

#define TC_LOAD_A(buf, Asrc, colbase)                                      \
    _Pragma("unroll")                                                      \
    for (int t = 0; t < 2; t++) {                                          \
        int idx = tid + t * 256;                                           \
        int r = idx >> 2, c = (idx & 3) * 4;                               \
        cp16(&As[buf][r][c],                                               \
             (Asrc) + (size_t)(row0 + r) * FDIM + (colbase) + c,           \
             (row0 + r) < N_NODES);                                        \
    }

#define TC_LOAD_W(buf, Wsrc, kb)                                           \
    _Pragma("unroll")                                                      \
    for (int t = 0; t < 2; t++) {                                          \
        int idx = tid + t * 256;                                           \
        int r = idx >> 5, c = (idx & 31) * 4;                              \
        cp16(&Ws[buf][r][c], (Wsrc) + (size_t)((kb) + r) * FDIM + c, true);\
    }

#define TC_COMPUTE(b)                                                      \
    _Pragma("unroll")                                                      \
    for (int ks = 0; ks < 16; ks += 8) {                                   \
        unsigned af[4][4], bf[4][2];                                       \
        _Pragma("unroll")                                                  \
        for (int m = 0; m < 4; m++) {                                      \
            int r = wr + 16 * m + qid;                                     \
            af[m][0] = __float_as_uint(As[b][r][ks + qtid]);               \
            af[m][1] = __float_as_uint(As[b][r + 8][ks + qtid]);           \
            af[m][2] = __float_as_uint(As[b][r][ks + qtid + 4]);           \
            af[m][3] = __float_as_uint(As[b][r + 8][ks + qtid + 4]);       \
        }                                                                  \
        _Pragma("unroll")                                                  \
        for (int n = 0; n < 4; n++) {                                      \
            int cc = wc + 8 * n + qid;                                     \
            bf[n][0] = __float_as_uint(Ws[b][ks + qtid][cc]);              \
            bf[n][1] = __float_as_uint(Ws[b][ks + qtid + 4][cc]);          \
        }                                                                  \
        _Pragma("unroll")                                                  \
        for (int m = 0; m < 4; m++)                                        \
            _Pragma("unroll")                                              \
            for (int n = 0; n < 4; n++)                                    \
                mma8(acc[m][n], af[m][0], af[m][1], af[m][2], af[m][3],    \
                     bf[n][0], bf[n][1]);                                  \
    }

__global__ void __launch_bounds__(256, 2)
k_final(const float* __restrict__ H, float* __restrict__ h_out) {
    const float* Wc = g_Wcomb[2];
    const float* cb = g_c[2];

    TC_DECL
    TC_LOAD_A(0, g_agg, 0)
    TC_LOAD_W(0, Wc, 0)
    CP_COMMIT;
    for (int kk = 0; kk < 16; kk++) {
        if (kk + 1 < 16) {
            int nk = kk + 1;
            const float* Asrc = (nk < 8) ? g_agg : g_R;   // g_R holds H*R
            TC_LOAD_A(nk & 1, Asrc, (nk & 7) * 16)
            TC_LOAD_W(nk & 1, Wc, nk * 16)
            CP_COMMIT; CP_WAIT1;
        } else { CP_WAIT0; }
        __syncthreads();
        TC_COMPUTE(kk & 1)
        __syncthreads();
    }
    #pragma unroll
    for (int m = 0; m < 4; m++) {
        #pragma unroll
        for (int n = 0; n < 4; n++) {
            int col = wc + 8 * n + 2 * qtid;
            float b0v = cb[col], b1v = cb[col + 1];
            #pragma unroll
            for (int h = 0; h < 2; h++) {
                int row = row0 + wr + 16 * m + qid + 8 * h;
                if (row < N_NODES) {
                    float2 zv = *(const float2*)(g_Z + (size_t)row * FDIM + col);
                    float2 hv = *(const float2*)(H + (size_t)row * FDIM + col);
                    float x0 = acc[m][n][2 * h] + b0v;
                    float x1 = acc[m][n][2 * h + 1] + b1v;
                    float t0 = 1.0f - 2.0f / (__expf(2.0f * x0) + 1.0f);
                    float t1 = 1.0f - 2.0f / (__expf(2.0f * x1) + 1.0f);
                    float2 hr;
                    hr.x = zv.x * hv.x + (1.0f - zv.x) * t0;
                    hr.y = zv.y * hv.y + (1.0f - zv.y) * t1;
                    *(float2*)(h_out + (size_t)row * FDIM + col) = hr;
                    float2 rl = make_float2(fmaxf(hr.x, 0.0f), fmaxf(hr.y, 0.0f));
                    *(float2*)(g_relu + (size_t)row * FDIM + col) = rl;
                }
            }
        }
    }
}

// ---------------- readout: y = relu(h) @ Wo + bo ------------------------------
__global__ void __launch_bounds__(128)
k_readout(const float* __restrict__ Wo, const float* __restrict__ bo,
          float* __restrict__ y_out) {
    __shared__ float Wos[FDIM * OUTD + OUTD];
    int tid = threadIdx.x;
    for (int t = tid; t < FDIM * OUTD; t += 128) Wos[t] = Wo[t];
    if (tid < OUTD) Wos[FDIM * OUTD + tid] = bo[tid];
    __syncthreads();
    int row = blockIdx.x * 128 + tid;
    if (row >= N_NODES) return;
    const float* hr = g_relu + (size_t)row * FDIM;
    float acc[OUTD] = {};
    #pragma unroll 4
    for (int k4 = 0; k4 < FDIM / 4; k4++) {
        float4 hv = *(const float4*)(hr + k4 * 4);
        float hvv[4] = {hv.x, hv.y, hv.z, hv.w};
        #pragma unroll
        for (int j = 0; j < 4; j++)
            #pragma unroll
            for (int o = 0; o < OUTD; o++)
                acc[o] += hvv[j] * Wos[(k4 * 4 + j) * OUTD + o];
    }
    #pragma unroll
    for (int o = 0; o < OUTD; o++)
        y_out[(size_t)row * OUTD + o] = acc[o] + Wos[FDIM * OUTD + o];
}

// ---------------- launch ------------------------------------------------------
extern "C" void kernel_launch(void* const* d_in, const int* in_sizes, int n_in,
                              void* d_out, int out_size) {
    const float* x  = (const float*)d_in[0];
    const int*   ei = (const int*)d_in[1];
    const float* ew = (const float*)d_in[2];
    const float* H  = (const float*)d_in[3];
    const float* Wz = (const float*)d_in[4];
    const float* bz = (const float*)d_in[5];
    const float* Wr = (const float*)d_in[6];
    const float* br = (const float*)d_in[7];
    const float* Wh = (const float*)d_in[8];
    const float* bh = (const float*)d_in[9];
    const float* Lz = (const float*)d_in[10];
    const float* lbz = (const float*)d_in[11];
    const float* Lr = (const float*)d_in[12];
    const float* lbr = (const float*)d_in[13];
    const float* Lh = (const float*)d_in[14];
    const float* lbh = (const float*)d_in[15];
    const float* Wo = (const float*)d_in[16];
    const float* bo = (const float*)d_in[17];

    float* y_out = (float*)d_out;                           // (N, 12)
    float* h_out = (float*)d_out + (size_t)N_NODES * OUTD;  // (N, 128)

    cudaFuncSetAttribute(k_zr, cudaFuncAttributeMaxDynamicSharedMemorySize,
                         ZR_SM_FLOATS * 4);

    int nblk = (N_NODES + 127) / 128;   // 391

    k_prep_m<<<dim3(2, 3), 256>>>(Wz, Wr, Wh, Lz, Lr, Lh);
    k_prep_rest<<<3, 256>>>(Lz, Lr, Lh, bz, br, bh, lbz, lbr, lbh);
    k_prep_zr<<<64, 256>>>();
    k_init_deg<<<(N_NODES + 255) / 256, 256>>>();
    k_deg_acc<<<592, 256>>>(ei, ew);
    k_dinv_self<<<(N_NODES * 32 + 255) / 256, 256>>>(x);
    k_edge_agg<<<(E_EDGES * 32 + 255) / 256, 256>>>(ei, ew, x);
    k_zr<<<nblk, 512, ZR_SM_FLOATS * 4>>>(H);
    k_final<<<nblk, 256>>>(H, h_out);
    k_readout<<<nblk, 128>>>(Wo, bo, y_out);
}

// round 15
// speedup vs baseline: 1.1665x; 1.1059x over previous
#include <cuda_runtime.h>
#include <cstdint>

#define N_NODES 50000
#define E_EDGES 600000
#define FDIM 128
#define OUTD 12

// ---------------- scratch (device globals; no runtime allocation) ------------
__device__ float g_deg[N_NODES];
__device__ float g_dinv[N_NODES];
__device__ float g_agg[(size_t)N_NODES * FDIM];          // A_norm @ x
__device__ float g_Z[(size_t)N_NODES * FDIM];
__device__ float g_R[(size_t)N_NODES * FDIM];            // stores H*R (fused)
__device__ float g_Wcomb[3][256 * FDIM];                 // [Mg ; Lg_bot] per gate
__device__ float g_c[3][FDIM];                           // folded biases

// ---------------- weight folding: Mg = Wg @ Lg_top ----------------------------
__global__ void __launch_bounds__(256)
k_prep_m(const float* __restrict__ Wz, const float* __restrict__ Wr,
         const float* __restrict__ Wh, const float* __restrict__ Lz,
         const float* __restrict__ Lr, const float* __restrict__ Lh) {
    int gate = blockIdx.y;
    const float* W = (gate == 0) ? Wz : (gate == 1) ? Wr : Wh;
    const float* L = (gate == 0) ? Lz : (gate == 1) ? Lr : Lh;
    float* C = g_Wcomb[gate];

    __shared__ float As[64][16];
    __shared__ float Ls[16][128];
    int tid = threadIdx.x, tx = tid & 31, ty = tid >> 5;
    int row0 = blockIdx.x * 64;
    float acc[8][4] = {};

    for (int kk = 0; kk < 128; kk += 16) {
        {
            int r = tid >> 2, c4 = tid & 3;
            *(float4*)&As[r][c4 * 4] =
                *(const float4*)(W + (size_t)(row0 + r) * FDIM + kk + c4 * 4);
        }
        #pragma unroll
        for (int t = 0; t < 2; t++) {
            int idx = tid + t * 256;
            int r = idx >> 5, c = (idx & 31) * 4;
            *(float4*)&Ls[r][c] = *(const float4*)(L + (size_t)(kk + r) * FDIM + c);
        }
        __syncthreads();
        #pragma unroll
        for (int k = 0; k < 16; k++) {
            float4 wv = *(float4*)&Ls[k][tx * 4];
            #pragma unroll
            for (int i = 0; i < 8; i++) {
                float a = As[ty * 8 + i][k];
                acc[i][0] += a * wv.x; acc[i][1] += a * wv.y;
                acc[i][2] += a * wv.z; acc[i][3] += a * wv.w;
            }
        }
        __syncthreads();
    }
    #pragma unroll
    for (int i = 0; i < 8; i++) {
        int row = row0 + ty * 8 + i;
        *(float4*)(C + (size_t)row * FDIM + tx * 4) =
            make_float4(acc[i][0], acc[i][1], acc[i][2], acc[i][3]);
    }
}

__global__ void __launch_bounds__(256)
k_prep_rest(const float* __restrict__ Lz, const float* __restrict__ Lr,
            const float* __restrict__ Lh,
            const float* __restrict__ bz, const float* __restrict__ br,
            const float* __restrict__ bh,
            const float* __restrict__ lbz, const float* __restrict__ lbr,
            const float* __restrict__ lbh) {
    int g = blockIdx.x;
    const float* L  = (g == 0) ? Lz : (g == 1) ? Lr : Lh;
    const float* b  = (g == 0) ? bz : (g == 1) ? br : bh;
    const float* lb = (g == 0) ? lbz : (g == 1) ? lbr : lbh;
    float* C = g_Wcomb[g];
    int tid = threadIdx.x;
    for (int i = tid; i < 128 * FDIM / 4; i += 256)
        ((float4*)(C + 128 * FDIM))[i] = ((const float4*)(L + 128 * FDIM))[i];
    if (tid < FDIM) {
        float a = lb[tid];
        #pragma unroll 8
        for (int k = 0; k < 128; k++) a += b[k] * L[(size_t)k * FDIM + tid];
        g_c[g][tid] = a;
    }
}

// ---------------- degree / norm / aggregation ---------------------------------
__global__ void k_init_deg() {
    int i = blockIdx.x * blockDim.x + threadIdx.x;
    if (i < N_NODES) g_deg[i] = 1.0f;
}

__global__ void k_deg_acc(const int* __restrict__ ei,
                          const float* __restrict__ ew) {
    for (int e = blockIdx.x * blockDim.x + threadIdx.x; e < E_EDGES;
         e += gridDim.x * blockDim.x) {
        int d = ei[E_EDGES + e];
        atomicAdd(&g_deg[d], ew[e]);
    }
}

__global__ void k_dinv_self(const float* __restrict__ x) {
    int warp = (blockIdx.x * blockDim.x + threadIdx.x) >> 5;
    int lane = threadIdx.x & 31;
    if (warp >= N_NODES) return;
    float s;
    if (lane == 0) {
        float dg = g_deg[warp];
        s = (dg > 0.0f) ? rsqrtf(dg) : 0.0f;
        g_dinv[warp] = s;
    }
    s = __shfl_sync(0xffffffffu, s, 0);
    float s2 = s * s;
    size_t off = (size_t)warp * FDIM + lane * 4;
    float4 v = *(const float4*)(x + off);
    v.x *= s2; v.y *= s2; v.z *= s2; v.w *= s2;
    *(float4*)(g_agg + off) = v;
}

__global__ void k_edge_agg(const int* __restrict__ ei,
                           const float* __restrict__ ew,
                           const float* __restrict__ x) {
    int warp = (blockIdx.x * blockDim.x + threadIdx.x) >> 5;
    int lane = threadIdx.x & 31;
    if (warp >= E_EDGES) return;
    int s = 0, d = 0;
    float norm = 0.0f;
    if (lane == 0) {
        s = ei[warp];
        d = ei[E_EDGES + warp];
        norm = g_dinv[s] * ew[warp] * g_dinv[d];
    }
    s = __shfl_sync(0xffffffffu, s, 0);
    d = __shfl_sync(0xffffffffu, d, 0);
    norm = __shfl_sync(0xffffffffu, norm, 0);
    float4 v = *(const float4*)(x + (size_t)s * FDIM + lane * 4);
    float* p = g_agg + (size_t)d * FDIM + lane * 4;
    asm volatile("red.global.add.v4.f32 [%0], {%1,%2,%3,%4};"
                 :: "l"(p), "f"(v.x * norm), "f"(v.y * norm),
                    "f"(v.z * norm), "f"(v.w * norm)
                 : "memory");
}

// ============= tf32 tensor-core GEMM, cp.async double-buffered ================
__device__ __forceinline__ void cp16(void* s, const void* g, bool pred) {
    unsigned sa = (unsigned)__cvta_generic_to_shared(s);
    int sz = pred ? 16 : 0;
    asm volatile("cp.async.cg.shared.global [%0], [%1], 16, %2;\n"
                 :: "r"(sa), "l"(g), "r"(sz));
}
#define CP_COMMIT asm volatile("cp.async.commit_group;\n" ::: "memory")
#define CP_WAIT1  asm volatile("cp.async.wait_group 1;\n" ::: "memory")
#define CP_WAIT0  asm volatile("cp.async.wait_group 0;\n" ::: "memory")

__device__ __forceinline__ void mma8(float* c, unsigned a0, unsigned a1,
                                     unsigned a2, unsigned a3,
                                     unsigned b0, unsigned b1) {
    asm volatile("mma.sync.aligned.m16n8k8.row.col.f32.tf32.tf32.f32 "
        "{%0,%1,%2,%3},{%4,%5,%6,%7},{%8,%9},{%0,%1,%2,%3};"
        : "+f"(c[0]), "+f"(c[1]), "+f"(c[2]), "+f"(c[3])
        : "r"(a0), "r"(a1), "r"(a2), "r"(a3), "r"(b0), "r"(b1));
}

// Block 128x128, 256 thr = 8 warps (2 row x 4 col), warp tile 64x32.
// K-chunk = 16, ping-pong. As stride 20, Ws stride 136: both conflict-free.
#define TC_DECL                                                            \
    __shared__ float As[2][128][20];                                       \
    __shared__ float Ws[2][16][136];                                       \
    int tid = threadIdx.x;                                                 \
    int lane = tid & 31, wid = tid >> 5;                                   \
    int qid = lane >> 2, qtid = lane & 3;                                  \
    int wr = (wid >> 2) * 64, wc = (wid & 3) * 32;                         \
    int row0 = blockIdx.x * 128;                                           \
    float acc[4][4][4] = {};

#define TC_LOAD_A(buf, Asrc, colbase)                                      \
    _Pragma("unroll")                                                      \
    for (int t = 0; t < 2; t++) {                                          \
        int idx = tid + t * 256;                                           \
        int r = idx >> 2, c = (idx & 3) * 4;                               \
        cp16(&As[buf][r][c],                                               \
             (Asrc) + (size_t)(row0 + r) * FDIM + (colbase) + c,           \
             (row0 + r) < N_NODES);                                        \
    }

#define TC_LOAD_W(buf, Wsrc, kb)                                           \
    _Pragma("unroll")                                                      \
    for (int t = 0; t < 2; t++) {                                          \
        int idx = tid + t * 256;                                           \
        int r = idx >> 5, c = (idx & 31) * 4;                              \
        cp16(&Ws[buf][r][c], (Wsrc) + (size_t)((kb) + r) * FDIM + c, true);\
    }

#define TC_COMPUTE(b)                                                      \
    _Pragma("unroll")                                                      \
    for (int ks = 0; ks < 16; ks += 8) {                                   \
        unsigned af[4][4], bf[4][2];                                       \
        _Pragma("unroll")                                                  \
        for (int m = 0; m < 4; m++) {                                      \
            int r = wr + 16 * m + qid;                                     \
            af[m][0] = __float_as_uint(As[b][r][ks + qtid]);               \
            af[m][1] = __float_as_uint(As[b][r + 8][ks + qtid]);           \
            af[m][2] = __float_as_uint(As[b][r][ks + qtid + 4]);           \
            af[m][3] = __float_as_uint(As[b][r + 8][ks + qtid + 4]);       \
        }                                                                  \
        _Pragma("unroll")                                                  \
        for (int n = 0; n < 4; n++) {                                      \
            int cc = wc + 8 * n + qid;                                     \
            bf[n][0] = __float_as_uint(Ws[b][ks + qtid][cc]);              \
            bf[n][1] = __float_as_uint(Ws[b][ks + qtid + 4][cc]);          \
        }                                                                  \
        _Pragma("unroll")                                                  \
        for (int m = 0; m < 4; m++)                                        \
            _Pragma("unroll")                                              \
            for (int n = 0; n < 4; n++)                                    \
                mma8(acc[m][n], af[m][0], af[m][1], af[m][2], af[m][3],    \
                     bf[n][0], bf[n][1]);                                  \
    }

// ------- GEMM A: Z = sig(...); R path stores H*R directly --------------------
__global__ void __launch_bounds__(256, 2)
k_zr_gemm(const float* __restrict__ H) {
    int which = blockIdx.y;          // 0=Z, 1=R(->H*R)
    const float* Wc = g_Wcomb[which];
    const float* cb = g_c[which];
    float* C = (which == 0) ? g_Z : g_R;

    TC_DECL
    TC_LOAD_A(0, g_agg, 0)
    TC_LOAD_W(0, Wc, 0)
    CP_COMMIT;
    for (int kk = 0; kk < 16; kk++) {
        if (kk + 1 < 16) {
            int nk = kk + 1;
            const float* Asrc = (nk < 8) ? g_agg : H;
            TC_LOAD_A(nk & 1, Asrc, (nk & 7) * 16)
            TC_LOAD_W(nk & 1, Wc, nk * 16)
            CP_COMMIT; CP_WAIT1;
        } else { CP_WAIT0; }
        __syncthreads();
        TC_COMPUTE(kk & 1)
        __syncthreads();
    }
    #pragma unroll
    for (int m = 0; m < 4; m++) {
        #pragma unroll
        for (int n = 0; n < 4; n++) {
            int col = wc + 8 * n + 2 * qtid;
            float b0v = cb[col], b1v = cb[col + 1];
            #pragma unroll
            for (int h = 0; h < 2; h++) {
                int row = row0 + wr + 16 * m + qid + 8 * h;
                if (row < N_NODES) {
                    float2 o;
                    o.x = 1.0f / (1.0f + __expf(-(acc[m][n][2 * h] + b0v)));
                    o.y = 1.0f / (1.0f + __expf(-(acc[m][n][2 * h + 1] + b1v)));
                    if (which == 1) {   // fuse H*R
                        float2 hv = *(const float2*)(H + (size_t)row * FDIM + col);
                        o.x *= hv.x; o.y *= hv.y;
                    }
                    *(float2*)(C + (size_t)row * FDIM + col) = o;
                }
            }
        }
    }
}

// ------ GEMM B: Ht = tanh(agg@Mh + (H*R)@Ph + ch); h = Z*H+(1-Z)*Ht;
//        relu(h) staged in smem; in-block readout y = relu(h)@Wo + bo ---------
// dynamic smem: RL[128][132] = 16896 fl | Wos[128*12+12] = 1548 fl = 73776 B
#define FIN_DYN_FLOATS (128 * 132 + FDIM * OUTD + OUTD)

__global__ void __launch_bounds__(256, 2)
k_final(const float* __restrict__ H, const float* __restrict__ Wo,
        const float* __restrict__ bo,
        float* __restrict__ y_out, float* __restrict__ h_out) {
    extern __shared__ float dyn_[];
    float* RL  = dyn_;                     // [128][132] relu(h)
    float* Wos = dyn_ + 128 * 132;         // Wo + bo

    const float* Wc = g_Wcomb[2];
    const float* cb = g_c[2];

    TC_DECL

    // stage Wo/bo early (dynamic smem unused by mainloop)
    for (int t = tid; t < FDIM * OUTD; t += 256) Wos[t] = Wo[t];
    if (tid < OUTD) Wos[FDIM * OUTD + tid] = bo[tid];

    TC_LOAD_A(0, g_agg, 0)
    TC_LOAD_W(0, Wc, 0)
    CP_COMMIT;
    for (int kk = 0; kk < 16; kk++) {
        if (kk + 1 < 16) {
            int nk = kk + 1;
            const float* Asrc = (nk < 8) ? g_agg : g_R;   // g_R holds H*R
            TC_LOAD_A(nk & 1, Asrc, (nk & 7) * 16)
            TC_LOAD_W(nk & 1, Wc, nk * 16)
            CP_COMMIT; CP_WAIT1;
        } else { CP_WAIT0; }
        __syncthreads();
        TC_COMPUTE(kk & 1)
        __syncthreads();
    }
    #pragma unroll
    for (int m = 0; m < 4; m++) {
        #pragma unroll
        for (int n = 0; n < 4; n++) {
            int col = wc + 8 * n + 2 * qtid;
            float b0v = cb[col], b1v = cb[col + 1];
            #pragma unroll
            for (int h = 0; h < 2; h++) {
                int rl = wr + 16 * m + qid + 8 * h;
                int row = row0 + rl;
                if (row < N_NODES) {
                    float2 zv = *(const float2*)(g_Z + (size_t)row * FDIM + col);
                    float2 hv = *(const float2*)(H + (size_t)row * FDIM + col);
                    float x0 = acc[m][n][2 * h] + b0v;
                    float x1 = acc[m][n][2 * h + 1] + b1v;
                    float t0 = 1.0f - 2.0f / (__expf(2.0f * x0) + 1.0f);
                    float t1 = 1.0f - 2.0f / (__expf(2.0f * x1) + 1.0f);
                    float2 hr;
                    hr.x = zv.x * hv.x + (1.0f - zv.x) * t0;
                    hr.y = zv.y * hv.y + (1.0f - zv.y) * t1;
                    *(float2*)(h_out + (size_t)row * FDIM + col) = hr;
                    RL[rl * 132 + col]     = fmaxf(hr.x, 0.0f);
                    RL[rl * 132 + col + 1] = fmaxf(hr.y, 0.0f);
                }
            }
        }
    }
    __syncthreads();

    // in-block readout: 2 threads per row, 6 out-cols each
    {
        int rl = tid >> 1;
        int og = (tid & 1) * 6;
        int grow = row0 + rl;
        if (grow < N_NODES) {
            float a[6] = {};
            #pragma unroll 8
            for (int k = 0; k < FDIM; k++) {
                float hv = RL[rl * 132 + k];
                #pragma unroll
                for (int o = 0; o < 6; o++)
                    a[o] += hv * Wos[k * OUTD + og + o];
            }
            #pragma unroll
            for (int o = 0; o < 6; o++)
                y_out[(size_t)grow * OUTD + og + o] = a[o] + Wos[FDIM * OUTD + og + o];
        }
    }
}

// ---------------- launch ------------------------------------------------------
extern "C" void kernel_launch(void* const* d_in, const int* in_sizes, int n_in,
                              void* d_out, int out_size) {
    const float* x  = (const float*)d_in[0];
    const int*   ei = (const int*)d_in[1];
    const float* ew = (const float*)d_in[2];
    const float* H  = (const float*)d_in[3];
    const float* Wz = (const float*)d_in[4];
    const float* bz = (const float*)d_in[5];
    const float* Wr = (const float*)d_in[6];
    const float* br = (const float*)d_in[7];
    const float* Wh = (const float*)d_in[8];
    const float* bh = (const float*)d_in[9];
    const float* Lz = (const float*)d_in[10];
    const float* lbz = (const float*)d_in[11];
    const float* Lr = (const float*)d_in[12];
    const float* lbr = (const float*)d_in[13];
    const float* Lh = (const float*)d_in[14];
    const float* lbh = (const float*)d_in[15];
    const float* Wo = (const float*)d_in[16];
    const float* bo = (const float*)d_in[17];

    float* y_out = (float*)d_out;                           // (N, 12)
    float* h_out = (float*)d_out + (size_t)N_NODES * OUTD;  // (N, 128)

    cudaFuncSetAttribute(k_final, cudaFuncAttributeMaxDynamicSharedMemorySize,
                         FIN_DYN_FLOATS * 4);

    int nblk = (N_NODES + 127) / 128;   // 391

    k_prep_m<<<dim3(2, 3), 256>>>(Wz, Wr, Wh, Lz, Lr, Lh);
    k_prep_rest<<<3, 256>>>(Lz, Lr, Lh, bz, br, bh, lbz, lbr, lbh);
    k_init_deg<<<(N_NODES + 255) / 256, 256>>>();
    k_deg_acc<<<592, 256>>>(ei, ew);
    k_dinv_self<<<(N_NODES * 32 + 255) / 256, 256>>>(x);
    k_edge_agg<<<(E_EDGES * 32 + 255) / 256, 256>>>(ei, ew, x);
    k_zr_gemm<<<dim3(nblk, 2), 256>>>(H);
    k_final<<<nblk, 256, FIN_DYN_FLOATS * 4>>>(H, Wo, bo, y_out, h_out);
}

// round 16
// speedup vs baseline: 1.2222x; 1.0477x over previous
#include <cuda_runtime.h>
#include <cstdint>

#define N_NODES 50000
#define E_EDGES 600000
#define FDIM 128
#define OUTD 12

// ---------------- scratch (device globals; no runtime allocation) ------------
__device__ float g_deg[N_NODES];
__device__ float g_dinv[N_NODES];
__device__ float g_agg[(size_t)N_NODES * FDIM];          // A_norm @ x
__device__ float g_Z[(size_t)N_NODES * FDIM];
__device__ float g_R[(size_t)N_NODES * FDIM];            // stores H*R (fused)
__device__ float g_Wcomb[3][256 * FDIM];                 // [Mg ; Lg_bot] per gate
__device__ float g_c[3][FDIM];                           // folded biases

// ------- weight folding: Mg = Wg @ Lg_top; also inits g_deg=1 (self-loop) ----
__global__ void __launch_bounds__(256)
k_prep_m(const float* __restrict__ Wz, const float* __restrict__ Wr,
         const float* __restrict__ Wh, const float* __restrict__ Lz,
         const float* __restrict__ Lr, const float* __restrict__ Lh) {
    int tid = threadIdx.x;
    // fold deg init here (runs before k_deg_acc in stream order)
    {
        int bid = blockIdx.y * gridDim.x + blockIdx.x;          // 0..5
        for (int i = bid * 256 + tid; i < N_NODES; i += 6 * 256)
            g_deg[i] = 1.0f;
    }

    int gate = blockIdx.y;
    const float* W = (gate == 0) ? Wz : (gate == 1) ? Wr : Wh;
    const float* L = (gate == 0) ? Lz : (gate == 1) ? Lr : Lh;
    float* C = g_Wcomb[gate];

    __shared__ float As[64][16];
    __shared__ float Ls[16][128];
    int tx = tid & 31, ty = tid >> 5;
    int row0 = blockIdx.x * 64;
    float acc[8][4] = {};

    for (int kk = 0; kk < 128; kk += 16) {
        {
            int r = tid >> 2, c4 = tid & 3;
            *(float4*)&As[r][c4 * 4] =
                *(const float4*)(W + (size_t)(row0 + r) * FDIM + kk + c4 * 4);
        }
        #pragma unroll
        for (int t = 0; t < 2; t++) {
            int idx = tid + t * 256;
            int r = idx >> 5, c = (idx & 31) * 4;
            *(float4*)&Ls[r][c] = *(const float4*)(L + (size_t)(kk + r) * FDIM + c);
        }
        __syncthreads();
        #pragma unroll
        for (int k = 0; k < 16; k++) {
            float4 wv = *(float4*)&Ls[k][tx * 4];
            #pragma unroll
            for (int i = 0; i < 8; i++) {
                float a = As[ty * 8 + i][k];
                acc[i][0] += a * wv.x; acc[i][1] += a * wv.y;
                acc[i][2] += a * wv.z; acc[i][3] += a * wv.w;
            }
        }
        __syncthreads();
    }
    #pragma unroll
    for (int i = 0; i < 8; i++) {
        int row = row0 + ty * 8 + i;
        *(float4*)(C + (size_t)row * FDIM + tx * 4) =
            make_float4(acc[i][0], acc[i][1], acc[i][2], acc[i][3]);
    }
}

__global__ void __launch_bounds__(256)
k_prep_rest(const float* __restrict__ Lz, const float* __restrict__ Lr,
            const float* __restrict__ Lh,
            const float* __restrict__ bz, const float* __restrict__ br,
            const float* __restrict__ bh,
            const float* __restrict__ lbz, const float* __restrict__ lbr,
            const float* __restrict__ lbh) {
    int g = blockIdx.x;
    const float* L  = (g == 0) ? Lz : (g == 1) ? Lr : Lh;
    const float* b  = (g == 0) ? bz : (g == 1) ? br : bh;
    const float* lb = (g == 0) ? lbz : (g == 1) ? lbr : lbh;
    float* C = g_Wcomb[g];
    int tid = threadIdx.x;
    for (int i = tid; i < 128 * FDIM / 4; i += 256)
        ((float4*)(C + 128 * FDIM))[i] = ((const float4*)(L + 128 * FDIM))[i];
    if (tid < FDIM) {
        float a = lb[tid];
        #pragma unroll 8
        for (int k = 0; k < 128; k++) a += b[k] * L[(size_t)k * FDIM + tid];
        g_c[g][tid] = a;
    }
}

// ---------------- degree / norm / aggregation ---------------------------------
__global__ void k_deg_acc(const int* __restrict__ ei,
                          const float* __restrict__ ew) {
    for (int e = blockIdx.x * blockDim.x + threadIdx.x; e < E_EDGES;
         e += gridDim.x * blockDim.x) {
        int d = ei[E_EDGES + e];
        atomicAdd(&g_deg[d], ew[e]);
    }
}

__global__ void k_dinv_self(const float* __restrict__ x) {
    int warp = (blockIdx.x * blockDim.x + threadIdx.x) >> 5;
    int lane = threadIdx.x & 31;
    if (warp >= N_NODES) return;
    float s;
    if (lane == 0) {
        float dg = g_deg[warp];
        s = (dg > 0.0f) ? rsqrtf(dg) : 0.0f;
        g_dinv[warp] = s;
    }
    s = __shfl_sync(0xffffffffu, s, 0);
    float s2 = s * s;
    size_t off = (size_t)warp * FDIM + lane * 4;
    float4 v = *(const float4*)(x + off);
    v.x *= s2; v.y *= s2; v.z *= s2; v.w *= s2;
    *(float4*)(g_agg + off) = v;
}

// one warp per TWO edges: batched index fetch + MLP-2 gathers + 2 v4 reds
__global__ void k_edge_agg(const int* __restrict__ ei,
                           const float* __restrict__ ew,
                           const float* __restrict__ x) {
    int warp = (blockIdx.x * blockDim.x + threadIdx.x) >> 5;
    int lane = threadIdx.x & 31;
    int e0 = warp * 2;
    if (e0 >= E_EDGES) return;
    int s = 0, d = 0;
    float nrm = 0.0f;
    if (lane < 2) {
        int e = e0 + lane;
        s = ei[e];
        d = ei[E_EDGES + e];
        nrm = g_dinv[s] * ew[e] * g_dinv[d];
    }
    int s0 = __shfl_sync(0xffffffffu, s, 0);
    int d0 = __shfl_sync(0xffffffffu, d, 0);
    float n0 = __shfl_sync(0xffffffffu, nrm, 0);
    int s1 = __shfl_sync(0xffffffffu, s, 1);
    int d1 = __shfl_sync(0xffffffffu, d, 1);
    float n1 = __shfl_sync(0xffffffffu, nrm, 1);

    float4 v0 = *(const float4*)(x + (size_t)s0 * FDIM + lane * 4);
    float4 v1 = *(const float4*)(x + (size_t)s1 * FDIM + lane * 4);
    float* p0 = g_agg + (size_t)d0 * FDIM + lane * 4;
    float* p1 = g_agg + (size_t)d1 * FDIM + lane * 4;
    asm volatile("red.global.add.v4.f32 [%0], {%1,%2,%3,%4};"
                 :: "l"(p0), "f"(v0.x * n0), "f"(v0.y * n0),
                    "f"(v0.z * n0), "f"(v0.w * n0) : "memory");
    asm volatile("red.global.add.v4.f32 [%0], {%1,%2,%3,%4};"
                 :: "l"(p1), "f"(v1.x * n1), "f"(v1.y * n1),
                    "f"(v1.z * n1), "f"(v1.w * n1) : "memory");
}

// ============= tf32 tensor-core GEMM, cp.async pipelines ======================
__device__ __forceinline__ void cp16(void* s, const void* g, bool pred) {
    unsigned sa = (unsigned)__cvta_generic_to_shared(s);
    int sz = pred ? 16 : 0;
    asm volatile("cp.async.cg.shared.global [%0], [%1], 16, %2;\n"
                 :: "r"(sa), "l"(g), "r"(sz));
}
#define CP_COMMIT asm volatile("cp.async.commit_group;\n" ::: "memory")
#define CP_WAIT1  asm volatile("cp.async.wait_group 1;\n" ::: "memory")
#define CP_WAIT0  asm volatile("cp.async.wait_group 0;\n" ::: "memory")

__device__ __forceinline__ void mma8(float* c, unsigned a0, unsigned a1,
                                     unsigned a2, unsigned a3,
                                     unsigned b0, unsigned b1) {
    asm volatile("mma.sync.aligned.m16n8k8.row.col.f32.tf32.tf32.f32 "
        "{%0,%1,%2,%3},{%4,%5,%6,%7},{%8,%9},{%0,%1,%2,%3};"
        : "+f"(c[0]), "+f"(c[1]), "+f"(c[2]), "+f"(c[3])
        : "r"(a0), "r"(a1), "r"(a2), "r"(a3), "r"(b0), "r"(b1));
}

// ------- GEMM A (3-stage, dynamic smem): Z / H*R -----------------------------
// dyn smem: As3[3][128][20]=7680 fl | Ws3[3][16][136]=6528 fl = 56832 B
#define ZR_DYN_FLOATS (7680 + 6528)

__global__ void __launch_bounds__(256, 2)
k_zr_gemm(const float* __restrict__ H) {
    extern __shared__ float zdyn_[];
    float* As3 = zdyn_;              // [buf][128][20]
    float* Ws3 = zdyn_ + 7680;       // [buf][16][136]

    int which = blockIdx.y;          // 0=Z, 1=R(->H*R)
    const float* Wc = g_Wcomb[which];
    const float* cb = g_c[which];
    float* C = (which == 0) ? g_Z : g_R;

    int tid = threadIdx.x;
    int lane = tid & 31, wid = tid >> 5;
    int qid = lane >> 2, qtid = lane & 3;
    int wr = (wid >> 2) * 64, wc = (wid & 3) * 32;
    int row0 = blockIdx.x * 128;
    float acc[4][4][4] = {};

#define Z3_LOAD_A(buf, Asrc, colbase)                                      \
    _Pragma("unroll")                                                      \
    for (int t = 0; t < 2; t++) {                                          \
        int idx = tid + t * 256;                                           \
        int r = idx >> 2, c = (idx & 3) * 4;                               \
        cp16(&As3[((buf) * 128 + r) * 20 + c],                             \
             (Asrc) + (size_t)(row0 + r) * FDIM + (colbase) + c,           \
             (row0 + r) < N_NODES);                                        \
    }
#define Z3_LOAD_W(buf, kb)                                                 \
    _Pragma("unroll")                                                      \
    for (int t = 0; t < 2; t++) {                                          \
        int idx = tid + t * 256;                                           \
        int r = idx >> 5, c = (idx & 31) * 4;                              \
        cp16(&Ws3[((buf) * 16 + r) * 136 + c],                             \
             Wc + (size_t)((kb) + r) * FDIM + c, true);                    \
    }

    Z3_LOAD_A(0, g_agg, 0)  Z3_LOAD_W(0, 0)   CP_COMMIT;
    Z3_LOAD_A(1, g_agg, 16) Z3_LOAD_W(1, 16)  CP_COMMIT;

    for (int kk = 0; kk < 16; kk++) {
        if (kk == 15) { CP_WAIT0; } else { CP_WAIT1; }
        __syncthreads();
        if (kk + 2 < 16) {
            int nk = kk + 2;
            const float* Asrc = (nk < 8) ? g_agg : H;
            Z3_LOAD_A(nk % 3, Asrc, (nk & 7) * 16)
            Z3_LOAD_W(nk % 3, nk * 16)
            CP_COMMIT;
        }
        {
            int b = kk % 3;
            #pragma unroll
            for (int ks = 0; ks < 16; ks += 8) {
                unsigned af[4][4], bf[4][2];
                #pragma unroll
                for (int m = 0; m < 4; m++) {
                    int r = wr + 16 * m + qid;
                    af[m][0] = __float_as_uint(As3[(b * 128 + r) * 20 + ks + qtid]);
                    af[m][1] = __float_as_uint(As3[(b * 128 + r + 8) * 20 + ks + qtid]);
                    af[m][2] = __float_as_uint(As3[(b * 128 + r) * 20 + ks + qtid + 4]);
                    af[m][3] = __float_as_uint(As3[(b * 128 + r + 8) * 20 + ks + qtid + 4]);
                }
                #pragma unroll
                for (int n = 0; n < 4; n++) {
                    int cc = wc + 8 * n + qid;
                    bf[n][0] = __float_as_uint(Ws3[(b * 16 + ks + qtid) * 136 + cc]);
                    bf[n][1] = __float_as_uint(Ws3[(b * 16 + ks + qtid + 4) * 136 + cc]);
                }
                #pragma unroll
                for (int m = 0; m < 4; m++)
                    #pragma unroll
                    for (int n = 0; n < 4; n++)
                        mma8(acc[m][n], af[m][0], af[m][1], af[m][2], af[m][3],
                             bf[n][0], bf[n][1]);
            }
        }
    }
    #pragma unroll
    for (int m = 0; m < 4; m++) {
        #pragma unroll
        for (int n = 0; n < 4; n++) {
            int col = wc + 8 * n + 2 * qtid;
            float b0v = cb[col], b1v = cb[col + 1];
            #pragma unroll
            for (int h = 0; h < 2; h++) {
                int row = row0 + wr + 16 * m + qid + 8 * h;
                if (row < N_NODES) {
                    float2 o;
                    o.x = 1.0f / (1.0f + __expf(-(acc[m][n][2 * h] + b0v)));
                    o.y = 1.0f / (1.0f + __expf(-(acc[m][n][2 * h + 1] + b1v)));
                    if (which == 1) {   // fuse H*R
                        float2 hv = *(const float2*)(H + (size_t)row * FDIM + col);
                        o.x *= hv.x; o.y *= hv.y;
                    }
                    *(float2*)(C + (size_t)row * FDIM + col) = o;
                }
            }
        }
    }
}

// ---- GEMM B (2-stage static smem, as R15): Ht/h + in-block readout ----------
#define TC_DECL                                                            \
    __shared__ float As[2][128][20];                                       \
    __shared__ float Ws[2][16][136];                                       \
    int tid = threadIdx.x;                                                 \
    int lane = tid & 31, wid = tid >> 5;                                   \
    int qid = lane >> 2, qtid = lane & 3;                                  \
    int wr = (wid >> 2) * 64, wc = (wid & 3) * 32;                         \
    int row0 = blockIdx.x * 128;                                           \
    float acc[4][4][4] = {};

#define TC_LOAD_A(buf, Asrc, colbase)                                      \
    _Pragma("unroll")                                                      \
    for (int t = 0; t < 2; t++) {                                          \
        int idx = tid + t * 256;                                           \
        int r = idx >> 2, c = (idx & 3) * 4;                               \
        cp16(&As[buf][r][c],                                               \
             (Asrc) + (size_t)(row0 + r) * FDIM + (colbase) + c,           \
             (row0 + r) < N_NODES);                                        \
    }

#define TC_LOAD_W(buf, Wsrc, kb)                                           \
    _Pragma("unroll")                                                      \
    for (int t = 0; t < 2; t++) {                                          \
        int idx = tid + t * 256;                                           \
        int r = idx >> 5, c = (idx & 31) * 4;                              \
        cp16(&Ws[buf][r][c], (Wsrc) + (size_t)((kb) + r) * FDIM + c, true);\
    }

#define TC_COMPUTE(b)                                                      \
    _Pragma("unroll")                                                      \
    for (int ks = 0; ks < 16; ks += 8) {                                   \
        unsigned af[4][4], bf[4][2];                                       \
        _Pragma("unroll")                                                  \
        for (int m = 0; m < 4; m++) {                                      \
            int r = wr + 16 * m + qid;                                     \
            af[m][0] = __float_as_uint(As[b][r][ks + qtid]);               \
            af[m][1] = __float_as_uint(As[b][r + 8][ks + qtid]);           \
            af[m][2] = __float_as_uint(As[b][r][ks + qtid + 4]);           \
            af[m][3] = __float_as_uint(As[b][r + 8][ks + qtid + 4]);       \
        }                                                                  \
        _Pragma("unroll")                                                  \
        for (int n = 0; n < 4; n++) {                                      \
            int cc = wc + 8 * n + qid;                                     \
            bf[n][0] = __float_as_uint(Ws[b][ks + qtid][cc]);              \
            bf[n][1] = __float_as_uint(Ws[b][ks + qtid + 4][cc]);          \
        }                                                                  \
        _Pragma("unroll")                                                  \
        for (int m = 0; m < 4; m++)                                        \
            _Pragma("unroll")                                              \
            for (int n = 0; n < 4; n++)                                    \
                mma8(acc[m][n], af[m][0], af[m][1], af[m][2], af[m][3],    \
                     bf[n][0], bf[n][1]);                                  \
    }

// dynamic smem: RL[128][132] = 16896 fl | Wos[128*12+12] = 1548 fl = 73776 B
#define FIN_DYN_FLOATS (128 * 132 + FDIM * OUTD + OUTD)

__global__ void __launch_bounds__(256, 2)
k_final(const float* __restrict__ H, const float* __restrict__ Wo,
        const float* __restrict__ bo,
        float* __restrict__ y_out, float* __restrict__ h_out) {
    extern __shared__ float dyn_[];
    float* RL  = dyn_;                     // [128][132] relu(h)
    float* Wos = dyn_ + 128 * 132;         // Wo + bo

    const float* Wc = g_Wcomb[2];
    const float* cb = g_c[2];

    TC_DECL

    for (int t = tid; t < FDIM * OUTD; t += 256) Wos[t] = Wo[t];
    if (tid < OUTD) Wos[FDIM * OUTD + tid] = bo[tid];

    TC_LOAD_A(0, g_agg, 0)
    TC_LOAD_W(0, Wc, 0)
    CP_COMMIT;
    for (int kk = 0; kk < 16; kk++) {
        if (kk + 1 < 16) {
            int nk = kk + 1;
            const float* Asrc = (nk < 8) ? g_agg : g_R;   // g_R holds H*R
            TC_LOAD_A(nk & 1, Asrc, (nk & 7) * 16)
            TC_LOAD_W(nk & 1, Wc, nk * 16)
            CP_COMMIT; CP_WAIT1;
        } else { CP_WAIT0; }
        __syncthreads();
        TC_COMPUTE(kk & 1)
        __syncthreads();
    }
    #pragma unroll
    for (int m = 0; m < 4; m++) {
        #pragma unroll
        for (int n = 0; n < 4; n++) {
            int col = wc + 8 * n + 2 * qtid;
            float b0v = cb[col], b1v = cb[col + 1];
            #pragma unroll
            for (int h = 0; h < 2; h++) {
                int rl = wr + 16 * m + qid + 8 * h;
                int row = row0 + rl;
                if (row < N_NODES) {
                    float2 zv = *(const float2*)(g_Z + (size_t)row * FDIM + col);
                    float2 hv = *(const float2*)(H + (size_t)row * FDIM + col);
                    float x0 = acc[m][n][2 * h] + b0v;
                    float x1 = acc[m][n][2 * h + 1] + b1v;
                    float t0 = 1.0f - 2.0f / (__expf(2.0f * x0) + 1.0f);
                    float t1 = 1.0f - 2.0f / (__expf(2.0f * x1) + 1.0f);
                    float2 hr;
                    hr.x = zv.x * hv.x + (1.0f - zv.x) * t0;
                    hr.y = zv.y * hv.y + (1.0f - zv.y) * t1;
                    *(float2*)(h_out + (size_t)row * FDIM + col) = hr;
                    RL[rl * 132 + col]     = fmaxf(hr.x, 0.0f);
                    RL[rl * 132 + col + 1] = fmaxf(hr.y, 0.0f);
                }
            }
        }
    }
    __syncthreads();

    {
        int rl = tid >> 1;
        int og = (tid & 1) * 6;
        int grow = row0 + rl;
        if (grow < N_NODES) {
            float a[6] = {};
            #pragma unroll 8
            for (int k = 0; k < FDIM; k++) {
                float hv = RL[rl * 132 + k];
                #pragma unroll
                for (int o = 0; o < 6; o++)
                    a[o] += hv * Wos[k * OUTD + og + o];
            }
            #pragma unroll
            for (int o = 0; o < 6; o++)
                y_out[(size_t)grow * OUTD + og + o] = a[o] + Wos[FDIM * OUTD + og + o];
        }
    }
}

// ---------------- launch ------------------------------------------------------
extern "C" void kernel_launch(void* const* d_in, const int* in_sizes, int n_in,
                              void* d_out, int out_size) {
    const float* x  = (const float*)d_in[0];
    const int*   ei = (const int*)d_in[1];
    const float* ew = (const float*)d_in[2];
    const float* H  = (const float*)d_in[3];
    const float* Wz = (const float*)d_in[4];
    const float* bz = (const float*)d_in[5];
    const float* Wr = (const float*)d_in[6];
    const float* br = (const float*)d_in[7];
    const float* Wh = (const float*)d_in[8];
    const float* bh = (const float*)d_in[9];
    const float* Lz = (const float*)d_in[10];
    const float* lbz = (const float*)d_in[11];
    const float* Lr = (const float*)d_in[12];
    const float* lbr = (const float*)d_in[13];
    const float* Lh = (const float*)d_in[14];
    const float* lbh = (const float*)d_in[15];
    const float* Wo = (const float*)d_in[16];
    const float* bo = (const float*)d_in[17];

    float* y_out = (float*)d_out;                           // (N, 12)
    float* h_out = (float*)d_out + (size_t)N_NODES * OUTD;  // (N, 128)

    cudaFuncSetAttribute(k_zr_gemm, cudaFuncAttributeMaxDynamicSharedMemorySize,
                         ZR_DYN_FLOATS * 4);
    cudaFuncSetAttribute(k_final, cudaFuncAttributeMaxDynamicSharedMemorySize,
                         FIN_DYN_FLOATS * 4);

    int nblk = (N_NODES + 127) / 128;   // 391

    k_prep_m<<<dim3(2, 3), 256>>>(Wz, Wr, Wh, Lz, Lr, Lh);
    k_prep_rest<<<3, 256>>>(Lz, Lr, Lh, bz, br, bh, lbz, lbr, lbh);
    k_deg_acc<<<592, 256>>>(ei, ew);
    k_dinv_self<<<(N_NODES * 32 + 255) / 256, 256>>>(x);
    k_edge_agg<<<(E_EDGES / 2 * 32 + 255) / 256, 256>>>(ei, ew, x);
    k_zr_gemm<<<dim3(nblk, 2), 256, ZR_DYN_FLOATS * 4>>>(H);
    k_final<<<nblk, 256, FIN_DYN_FLOATS * 4>>>(H, Wo, bo, y_out, h_out);
}